// round 8
// baseline (speedup 1.0000x reference)
#include <cuda_runtime.h>
#include <cuda_fp16.h>
#include <math.h>

// Problem constants (fixed by the dataset)
#define E_NUM 32768
#define BATCH 128     // == H
#define DIM   1024    // IMG_DIM == TXT_DIM

// ---- device scratch (allocation-free: __device__ globals) ----
__device__ __align__(16) float  g_imgT [DIM * BATCH];   // img^T  [i][b]
__device__ __align__(16) float  g_txtT [DIM * BATCH];   // text^T [t][b]
__device__ __align__(16) float  g_W1aT [BATCH * BATCH]; // W1[:, :128]^T [b][j]
__device__ __align__(16) float  g_W1bT [BATCH * BATCH]; // W1[:, 128:]^T [b][j]
__device__ __align__(16) __half g_UTh  [DIM * BATCH];   // (W1a@img + b1)^T fp16
__device__ __align__(16) __half g_VTh  [DIM * BATCH];   // (W1b@text)^T     fp16
__device__ __align__(16) float  g_oImgT[DIM * BATCH];   // attended_img^T  [i][b]
__device__ __align__(16) float  g_oTxtT[DIM * BATCH];   // attended_text^T [t][b]

// ---- vectorized fused transposes. PDL: overlaps the previous replay's tail.
// 144 blocks x 512 threads; each block transposes a 128-row x 16-col strip of
// one input matrix into 16 output rows of 128 (float4 in, float4 out).
// blocks [0,64): img   [128x1024] -> g_imgT
// blocks [64,128): txt [128x1024] -> g_txtT
// blocks [128,136): W1a [128 x cols 0..127 of 256]  -> g_W1aT
// blocks [136,144): W1b [128 x cols 128..255 of 256] -> g_W1bT
__global__ void __launch_bounds__(512) k_prep(const float* __restrict__ img,
                                              const float* __restrict__ txt,
                                              const float* __restrict__ W1) {
    __shared__ __align__(16) float sh[16 * 132];   // [c][r], row length 132 (16B-aligned)
    int id = blockIdx.x;
    int t  = threadIdx.x;

    const float* in; float* o; int stride, c0;
    if (id < 64)        { in = img;        stride = DIM;       o = g_imgT; c0 = id * 16; }
    else if (id < 128)  { in = txt;        stride = DIM;       o = g_txtT; c0 = (id - 64) * 16; }
    else if (id < 136)  { in = W1;         stride = 2 * BATCH; o = g_W1aT; c0 = (id - 128) * 16; }
    else                { in = W1 + BATCH; stride = 2 * BATCH; o = g_W1bT; c0 = (id - 136) * 16; }

    // load: 128 rows x 16 cols as float4 (512 loads, 1/thread)
    {
        int r = t >> 2, x = t & 3;
        float4 v = *reinterpret_cast<const float4*>(in + (long)r * stride + c0 + 4 * x);
        sh[(4 * x + 0) * 132 + r] = v.x;
        sh[(4 * x + 1) * 132 + r] = v.y;
        sh[(4 * x + 2) * 132 + r] = v.z;
        sh[(4 * x + 3) * 132 + r] = v.w;
    }
    __syncthreads();

    // store: 16 output rows x 128 as float4 (512 stores, 1/thread)
    {
        int c = t >> 5, k = t & 31;
        float4 v = reinterpret_cast<const float4*>(sh + c * 132)[k];
        reinterpret_cast<float4*>(o + (c0 + c) * BATCH)[k] = v;
    }
}

// ---- UT[s][j] = b1[j] + sum_b W1aT[b][j]*imgT[s][b]   (stored fp16)
//      VT[t][j] =         sum_b W1bT[b][j]*txtT[t][b]   (stored fp16)
// PDL: zero accumulators (independent of k_prep) BEFORE the dependency sync.
__global__ void k_uv(const float* __restrict__ b1) {
    int  col = blockIdx.x & (DIM - 1);
    bool isV = blockIdx.x >= DIM;
    int  j   = threadIdx.x;

    // fused accumulator zeroing for the scatter phase (no upstream dependency)
    int zidx = col * BATCH + j;
    (isV ? g_oTxtT : g_oImgT)[zidx] = 0.0f;

    float bias = isV ? 0.0f : b1[j];   // kernel input, not produced upstream

    // now wait for k_prep's transposes
    cudaGridDependencySynchronize();

    const float* x  = (isV ? g_txtT : g_imgT) + col * BATCH;
    const float* Wt =  isV ? g_W1bT : g_W1aT;

    __shared__ float xs[BATCH];
    xs[j] = x[j];
    __syncthreads();

    float acc = bias;
#pragma unroll 16
    for (int b = 0; b < BATCH; ++b)
        acc = fmaf(Wt[b * BATCH + j], xs[b], acc);

    (isV ? g_VTh : g_UTh)[col * BATCH + j] = __float2half_rn(acc);
}

// ---- per-edge: a = sigmoid(w2 . relu(UT[s] + VT[t]) + b2), then scatter:
//      oImgT[s][:] += a * txtT[t][:];  oTxtT[t][:] += a * imgT[s][:]
// fp16 u/v gathers (8B/lane), fp32 feature gathers + v4-RED scatter.
__global__ void k_edge(const int* __restrict__ src, const int* __restrict__ tgt,
                       const float* __restrict__ w2, const float* __restrict__ b2) {
    int warp = threadIdx.x >> 5;
    int lane = threadIdx.x & 31;
    int e    = blockIdx.x * 8 + warp;

    int s = src[e];
    int t = tgt[e];
    float4 w = reinterpret_cast<const float4*>(w2)[lane];
    float bias2 = b2[0];

    // wait for k_uv (UT/VT + zeroed accumulators)
    cudaGridDependencySynchronize();

    uint2 ur = reinterpret_cast<const uint2*>(g_UTh + s * BATCH)[lane];
    uint2 vr = reinterpret_cast<const uint2*>(g_VTh + t * BATCH)[lane];
    float2 u01 = __half22float2(*reinterpret_cast<__half2*>(&ur.x));
    float2 u23 = __half22float2(*reinterpret_cast<__half2*>(&ur.y));
    float2 v01 = __half22float2(*reinterpret_cast<__half2*>(&vr.x));
    float2 v23 = __half22float2(*reinterpret_cast<__half2*>(&vr.y));

    float h0 = fmaxf(u01.x + v01.x, 0.0f);
    float h1 = fmaxf(u01.y + v01.y, 0.0f);
    float h2 = fmaxf(u23.x + v23.x, 0.0f);
    float h3 = fmaxf(u23.y + v23.y, 0.0f);

    float p = fmaf(h0, w.x, fmaf(h1, w.y, fmaf(h2, w.z, h3 * w.w)));
#pragma unroll
    for (int off = 16; off; off >>= 1)
        p += __shfl_xor_sync(0xffffffffu, p, off);

    float a = __fdividef(1.0f, 1.0f + __expf(-(p + bias2)));

    float4 tx = reinterpret_cast<const float4*>(g_txtT + t * BATCH)[lane];
    float4 im = reinterpret_cast<const float4*>(g_imgT + s * BATCH)[lane];

    float* oi = g_oImgT + s * BATCH + lane * 4;
    float* ot = g_oTxtT + t * BATCH + lane * 4;

    asm volatile("red.global.v4.f32.add [%0], {%1, %2, %3, %4};"
                 :: "l"(oi), "f"(a * tx.x), "f"(a * tx.y), "f"(a * tx.z), "f"(a * tx.w)
                 : "memory");
    asm volatile("red.global.v4.f32.add [%0], {%1, %2, %3, %4};"
                 :: "l"(ot), "f"(a * im.x), "f"(a * im.y), "f"(a * im.z), "f"(a * im.w)
                 : "memory");
}

// ---- final transpose of accumulators into the output layout ----
__global__ void k_writeout(float* __restrict__ out) {
    // out[0 .. 128*1024)          = attended_img  [b][i] = oImgT[i][b]
    // out[128*1024 .. 2*128*1024) = attended_text [b][t] = oTxtT[t][b]
    cudaGridDependencySynchronize();   // wait for k_edge's scatters

    __shared__ float tile[32][33];
    bool second = blockIdx.z != 0;
    const float* in = second ? g_oTxtT : g_oImgT;
    float* o = out + (second ? (size_t)BATCH * DIM : 0);

    int x = blockIdx.x * 32 + threadIdx.x;   // b  (input col, 0..127)
    int y = blockIdx.y * 32 + threadIdx.y;   // i/t (input row, 0..1023)
    tile[threadIdx.y][threadIdx.x] = in[(long)y * BATCH + x];
    __syncthreads();
    int ox = blockIdx.y * 32 + threadIdx.x;  // i/t
    int oy = blockIdx.x * 32 + threadIdx.y;  // b
    o[(long)oy * DIM + ox] = tile[threadIdx.x][threadIdx.y];
}

extern "C" void kernel_launch(void* const* d_in, const int* in_sizes, int n_in,
                              void* d_out, int out_size) {
    const float* img = (const float*)d_in[0];   // [128, 1024]
    const float* txt = (const float*)d_in[1];   // [128, 1024]
    const int*   src = (const int*)  d_in[2];   // [32768]
    const int*   tgt = (const int*)  d_in[3];   // [32768]
    const float* W1  = (const float*)d_in[4];   // [128, 256]
    const float* b1  = (const float*)d_in[5];   // [128]
    const float* w2  = (const float*)d_in[6];   // [128]
    const float* b2  = (const float*)d_in[7];   // [1]
    float* out = (float*)d_out;                 // [2 * 128 * 1024]

    cudaLaunchAttribute attr;
    attr.id = cudaLaunchAttributeProgrammaticStreamSerialization;
    attr.val.programmaticStreamSerializationAllowed = 1;

    // 1) vectorized fused transposes
    {
        cudaLaunchConfig_t cfg = {};
        cfg.gridDim  = dim3(144);
        cfg.blockDim = dim3(512);
        cfg.attrs = &attr;
        cfg.numAttrs = 1;
        cudaLaunchKernelEx(&cfg, k_prep, img, txt, W1);
    }

    // 2) U/V GEMMs (fp16 out) + accumulator zeroing
    {
        cudaLaunchConfig_t cfg = {};
        cfg.gridDim  = dim3(2 * DIM);
        cfg.blockDim = dim3(BATCH);
        cfg.attrs = &attr;
        cfg.numAttrs = 1;
        cudaLaunchKernelEx(&cfg, k_uv, b1);
    }

    // 3) per-edge MLP + vectorized scatter-accumulate
    {
        cudaLaunchConfig_t cfg = {};
        cfg.gridDim  = dim3(E_NUM / 8);
        cfg.blockDim = dim3(256);
        cfg.attrs = &attr;
        cfg.numAttrs = 1;
        cudaLaunchKernelEx(&cfg, k_edge, src, tgt, w2, b2);
    }

    // 4) transpose accumulators into the output layout
    {
        cudaLaunchConfig_t cfg = {};
        cfg.gridDim  = dim3(BATCH / 32, DIM / 32, 2);
        cfg.blockDim = dim3(32, 32);
        cfg.attrs = &attr;
        cfg.numAttrs = 1;
        cudaLaunchKernelEx(&cfg, k_writeout, out);
    }
}